// round 12
// baseline (speedup 1.0000x reference)
#include <cuda_runtime.h>
#include <cuda_fp16.h>
#include <math.h>
#include <stdint.h>

// Problem constants
#define D_MODEL 1024
#define NHEAD   16
#define HD      64
#define SEQ     2048
#define BATCH   2
#define NTOK    (BATCH * SEQ)          // 4096
#define QKV_LD  (3 * D_MODEL)          // 3072

// Q pre-scale: 1/sqrt(64) * log2(e)  (softmax done base-2)
#define QSCALE 0.18033688011112042f

// HBM scratch (no cudaMalloc allowed)
__device__ __half g_xh[(size_t)NTOK * D_MODEL];
__device__ __half g_wqkvTh[(size_t)QKV_LD * D_MODEL];
__device__ __half g_woutTh[(size_t)D_MODEL * D_MODEL];
__device__ __half g_qkvh[(size_t)NTOK * QKV_LD];          // Q(scaled)/K fp16
__device__ __half g_vt[(size_t)BATCH * NHEAD * HD * SEQ]; // V^T fp16 [bh][d][s]
__device__ __half g_atth[(size_t)NTOK * D_MODEL];

// ---------------------------------------------------------------------------
__device__ __forceinline__ uint32_t smem_u32(const void* p) {
    uint32_t a;
    asm("{ .reg .u64 t; cvta.to.shared.u64 t, %1; cvt.u32.u64 %0, t; }"
        : "=r"(a) : "l"(p));
    return a;
}
__device__ __forceinline__ unsigned h2_to_u32(__half2 h) {
    return *reinterpret_cast<unsigned*>(&h);
}
__device__ __forceinline__ float2 u32_to_f2(unsigned u) {
    __half2 h = *reinterpret_cast<__half2*>(&u);
    return __half22float2(h);
}
__device__ __forceinline__ void mma_f16(float c[4], const unsigned a[4],
                                        unsigned b0, unsigned b1) {
    asm volatile(
        "mma.sync.aligned.m16n8k16.row.col.f32.f16.f16.f32 "
        "{%0,%1,%2,%3}, {%4,%5,%6,%7}, {%8,%9}, {%0,%1,%2,%3};"
        : "+f"(c[0]), "+f"(c[1]), "+f"(c[2]), "+f"(c[3])
        : "r"(a[0]), "r"(a[1]), "r"(a[2]), "r"(a[3]), "r"(b0), "r"(b1));
}
__device__ __forceinline__ void ldsm_x4(unsigned& r0, unsigned& r1,
                                        unsigned& r2, unsigned& r3, uint32_t a) {
    asm volatile("ldmatrix.sync.aligned.m8n8.x4.shared.b16 {%0,%1,%2,%3}, [%4];"
                 : "=r"(r0), "=r"(r1), "=r"(r2), "=r"(r3) : "r"(a));
}
__device__ __forceinline__ unsigned ex2_h2(float lo, float hi) {
    unsigned r;
    asm("{\n\t.reg .b32 t;\n\tcvt.rn.f16x2.f32 t, %2, %1;\n\t"
        "ex2.approx.f16x2 %0, t;\n\t}"
        : "=r"(r) : "f"(lo), "f"(hi));
    return r;
}
#define CP16(dst, src) \
    asm volatile("cp.async.cg.shared.global [%0], [%1], 16;" \
                 :: "r"(dst), "l"(src) : "memory")
#define CP_COMMIT() asm volatile("cp.async.commit_group;" ::: "memory")
#define CP_WAIT(n)  asm volatile("cp.async.wait_group %0;" :: "n"(n) : "memory")

// ---------------------------------------------------------------------------
// Pre-passes
// ---------------------------------------------------------------------------
__global__ __launch_bounds__(256) void cvt_h_kernel(
    const float4* __restrict__ src, uint4* __restrict__ dst, int n8)
{
    for (int i = blockIdx.x * 256 + threadIdx.x; i < n8; i += gridDim.x * 256) {
        float4 a = src[2 * i], b = src[2 * i + 1];
        uint4 o;
        o.x = h2_to_u32(__floats2half2_rn(a.x, a.y));
        o.y = h2_to_u32(__floats2half2_rn(a.z, a.w));
        o.z = h2_to_u32(__floats2half2_rn(b.x, b.y));
        o.w = h2_to_u32(__floats2half2_rn(b.z, b.w));
        dst[i] = o;
    }
}

__global__ void transpose_cvt_kernel(
    const float* __restrict__ in, __half* __restrict__ out, int R, int C)
{
    __shared__ float t[32][33];
    const int bx = blockIdx.x * 32;
    const int by = blockIdx.y * 32;
    const int x = threadIdx.x, y = threadIdx.y;
#pragma unroll
    for (int j = 0; j < 32; j += 8)
        t[y + j][x] = in[(size_t)(by + y + j) * C + bx + x];
    __syncthreads();
#pragma unroll
    for (int j = 0; j < 32; j += 8)
        out[(size_t)(bx + y + j) * R + by + x] = __float2half(t[x][y + j]);
}

// ---------------------------------------------------------------------------
// FP16 mma GEMM: CTA 128x128, 4 warps of 64x64 (R7 shape), K-chunk 64,
// 3-stage cp.async pipeline (prefetch depth 2), LDSM fragment loads.
// As [m][k], Bs [n][k], row stride 72 half (144 B -> LDSM phase-distinct).
// mode 0: fp32 out.  mode 1: qkv (Q scaled by QSCALE, K fp16, V -> g_vt).
// ---------------------------------------------------------------------------
#define HSTR 72
#define A_ST_H (128 * HSTR)              // 9216 half
#define STG_H  (2 * A_ST_H)              // 18432 half per stage (A + B)
#define GEMM_SMEM_BYTES (3 * STG_H * 2)  // 110592

__global__ __launch_bounds__(128, 2) void gemm_h_kernel(
    const __half* __restrict__ A, const __half* __restrict__ Bt,
    const float* __restrict__ bias, void* __restrict__ Cout,
    int M, int N, int K, int mode)
{
    extern __shared__ __half smh[];
    const uint32_t smb = smem_u32(smh);

    const int tid  = threadIdx.x;
    const int lane = tid & 31;
    const int warp = tid >> 5;
    const int r4 = lane >> 2;
    const int c4 = lane & 3;
    const int wrow = (warp >> 1) * 64;
    const int wcol = (warp & 1) * 64;
    const int row0 = blockIdx.y * 128;
    const int col0 = blockIdx.x * 128;

    const __half* Ablk = A  + (size_t)row0 * K;
    const __half* Bblk = Bt + (size_t)col0 * K;

    // LDSM lane offsets (half units), stride 72
    const uint32_t loffA = (uint32_t)((lane & 15) * HSTR + (lane >> 4) * 8);
    const uint32_t loffB = (uint32_t)(((lane >> 4) * 8 + (lane & 7)) * HSTR
                                      + ((lane >> 3) & 1) * 8);

    // chunk = 64 k: A 128 rows x 4 float4, B same -> 8 CP16 per thread
#define GSTAGE(c, st) do {                                                   \
        const __half* Ag = Ablk + (c) * 64;                                  \
        const __half* Bg = Bblk + (c) * 64;                                  \
        _Pragma("unroll")                                                    \
        for (int i = 0; i < 4; i++) {                                        \
            const int id = tid + 128 * i;                                    \
            const int r = id >> 2, ch = id & 3;                              \
            CP16(smb + (uint32_t)(((st) * STG_H + r * HSTR + ch * 16) * 2),  \
                 Ag + (size_t)r * K + ch * 16);                              \
            CP16(smb + (uint32_t)(((st) * STG_H + r * HSTR + ch * 16 + 8) * 2), \
                 Ag + (size_t)r * K + ch * 16 + 8);                          \
            CP16(smb + (uint32_t)(((st) * STG_H + A_ST_H + r * HSTR + ch * 16) * 2), \
                 Bg + (size_t)r * K + ch * 16);                              \
            CP16(smb + (uint32_t)(((st) * STG_H + A_ST_H + r * HSTR + ch * 16 + 8) * 2), \
                 Bg + (size_t)r * K + ch * 16 + 8);                          \
        }                                                                    \
        CP_COMMIT();                                                         \
    } while (0)

    float acc[4][8][4];
#pragma unroll
    for (int mf = 0; mf < 4; mf++)
#pragma unroll
        for (int nf = 0; nf < 8; nf++)
#pragma unroll
            for (int x = 0; x < 4; x++) acc[mf][nf][x] = 0.f;

    const int nchunk = K / 64;   // 16
    GSTAGE(0, 0);
    GSTAGE(1, 1);

    int st = 0;
    for (int c = 0; c < nchunk; c++) {
        CP_WAIT(1);
        __syncthreads();

        // prefetch chunk c+2 into the buffer freed last iteration
        if (c + 2 < nchunk) {
            const int st2 = (st + 2 >= 3) ? (st - 1) : (st + 2);
            GSTAGE(c + 2, st2);
        } else {
            CP_COMMIT();
        }

        const uint32_t stA = smb + (uint32_t)((st * STG_H) * 2);
        const uint32_t stB = stA + (uint32_t)(A_ST_H * 2);

#pragma unroll
        for (int ks = 0; ks < 4; ks++) {
            unsigned af[4][4];
            const uint32_t aB = stA + (uint32_t)((wrow * HSTR + ks * 16 + loffA) * 2);
#pragma unroll
            for (int mf = 0; mf < 4; mf++)
                ldsm_x4(af[mf][0], af[mf][1], af[mf][2], af[mf][3],
                        aB + (uint32_t)(mf * 16 * HSTR * 2));
            unsigned bf0[8], bf1[8];
            const uint32_t bB = stB + (uint32_t)((wcol * HSTR + ks * 16 + loffB) * 2);
#pragma unroll
            for (int np = 0; np < 4; np++) {
                unsigned r0, r1, r2, r3;
                ldsm_x4(r0, r1, r2, r3, bB + (uint32_t)(np * 16 * HSTR * 2));
                bf0[2 * np] = r0; bf1[2 * np] = r1;
                bf0[2 * np + 1] = r2; bf1[2 * np + 1] = r3;
            }
#pragma unroll
            for (int nf = 0; nf < 8; nf++)
#pragma unroll
                for (int mf = 0; mf < 4; mf++)
                    mma_f16(acc[mf][nf], af[mf], bf0[nf], bf1[nf]);
        }

        st = (st + 1 >= 3) ? 0 : (st + 1);
    }

    // ---- epilogue ----
    if (mode == 0) {
        float* C = (float*)Cout;
#pragma unroll
        for (int mf = 0; mf < 4; mf++) {
            const int r = row0 + wrow + mf * 16 + r4;
#pragma unroll
            for (int nf = 0; nf < 8; nf++) {
                const int cc = col0 + wcol + nf * 8 + 2 * c4;
                const float bx = bias[cc], by = bias[cc + 1];
                *(float2*)&C[(size_t)r * N + cc] =
                    make_float2(acc[mf][nf][0] + bx, acc[mf][nf][1] + by);
                *(float2*)&C[(size_t)(r + 8) * N + cc] =
                    make_float2(acc[mf][nf][2] + bx, acc[mf][nf][3] + by);
            }
        }
    } else {
        const int cb  = col0 + wcol;
        const int h   = cb / 192;
        const int sec = (cb % 192) / 64;
        if (sec < 2) {
            const float sc = (sec == 0) ? QSCALE : 1.0f;
#pragma unroll
            for (int mf = 0; mf < 4; mf++) {
                const int r = row0 + wrow + mf * 16 + r4;
#pragma unroll
                for (int nf = 0; nf < 8; nf++) {
                    const int cc = cb + nf * 8 + 2 * c4;
                    const float bx = bias[cc], by = bias[cc + 1];
                    __half2 v0 = __floats2half2_rn((acc[mf][nf][0] + bx) * sc,
                                                   (acc[mf][nf][1] + by) * sc);
                    __half2 v1 = __floats2half2_rn((acc[mf][nf][2] + bx) * sc,
                                                   (acc[mf][nf][3] + by) * sc);
                    *(__half2*)&g_qkvh[(size_t)r * QKV_LD + cc] = v0;
                    *(__half2*)&g_qkvh[(size_t)(r + 8) * QKV_LD + cc] = v1;
                }
            }
        } else {
#pragma unroll
            for (int mf = 0; mf < 4; mf++) {
                const int r = row0 + wrow + mf * 16 + r4;
                const int bb = r >> 11, s = r & 2047;
                const int bb8 = (r + 8) >> 11, s8 = (r + 8) & 2047;
#pragma unroll
                for (int nf = 0; nf < 8; nf++) {
                    const int cc = cb + nf * 8 + 2 * c4;
                    const int d = (cc % 192) - 128;
                    const float bx = bias[cc], by = bias[cc + 1];
                    __half* v0 = g_vt + ((size_t)(bb * NHEAD + h) * HD + d) * SEQ;
                    v0[s]        = __float2half(acc[mf][nf][0] + bx);
                    v0[SEQ + s]  = __float2half(acc[mf][nf][1] + by);
                    __half* v8 = g_vt + ((size_t)(bb8 * NHEAD + h) * HD + d) * SEQ;
                    v8[s8]       = __float2half(acc[mf][nf][2] + bx);
                    v8[SEQ + s8] = __float2half(acc[mf][nf][3] + by);
                }
            }
        }
    }
#undef GSTAGE
}

// ---------------------------------------------------------------------------
// FlashAttention fp16 mma (R7 best, unchanged): P in registers,
// base-2 softmax via ex2.approx.f16x2, LDSM K/V frags, cp.async dbl-buffer.
// 4 warps x 16 q = 64 q/CTA, 64-key tiles.
// ---------------------------------------------------------------------------
#define TKSTR 72
#define KOFF(bi) ((bi) * 4608)
#define VOFF(bi) (9216 + (bi) * 4608)
#define ATT_SMEM_BYTES (18432 * 2)

__global__ __launch_bounds__(128, 3) void attn_h_kernel()
{
    extern __shared__ __half smh[];
    const uint32_t smb = smem_u32(smh);
    const int tid  = threadIdx.x;
    const int lane = tid & 31;
    const int warp = tid >> 5;
    const int b  = blockIdx.z;
    const int h  = blockIdx.y;
    const int q0 = blockIdx.x * 64;
    const int r4 = lane >> 2;
    const int c4 = lane & 3;

    const uint32_t loffT = (uint32_t)(((lane >> 4) * 8 + (lane & 7)) * TKSTR
                                      + ((lane >> 3) & 1) * 8);

    unsigned qf[4][4];
    {
        const __half* qr  = g_qkvh + (size_t)(b * SEQ + q0 + warp * 16 + r4) * QKV_LD + h * 192;
        const __half* qr8 = qr + (size_t)8 * QKV_LD;
#pragma unroll
        for (int kk = 0; kk < 4; kk++) {
            const int k0 = kk * 16 + 2 * c4;
            qf[kk][0] = *(const unsigned*)(qr + k0);
            qf[kk][1] = *(const unsigned*)(qr8 + k0);
            qf[kk][2] = *(const unsigned*)(qr + k0 + 8);
            qf[kk][3] = *(const unsigned*)(qr8 + k0 + 8);
        }
    }

    const __half* Kg = g_qkvh + (size_t)b * SEQ * QKV_LD + h * 192 + 64;
    const __half* Vg = g_vt + (size_t)(b * NHEAD + h) * HD * SEQ;

#define ASTAGE(t, bi) do {                                                   \
        const __half* Kt = Kg + (size_t)(t) * 64 * QKV_LD;                   \
        const __half* Vt = Vg + (t) * 64;                                    \
        _Pragma("unroll")                                                    \
        for (int i = 0; i < 4; i++) {                                        \
            const int id = tid + 128 * i;                                    \
            const int r = id >> 3, ch = id & 7;                              \
            CP16(smb + (uint32_t)((KOFF(bi) + r * TKSTR + ch * 8) * 2),      \
                 Kt + (size_t)r * QKV_LD + ch * 8);                          \
            CP16(smb + (uint32_t)((VOFF(bi) + r * TKSTR + ch * 8) * 2),      \
                 Vt + (size_t)r * SEQ + ch * 8);                             \
        }                                                                    \
        CP_COMMIT();                                                         \
    } while (0)

    float oacc[8][4];
#pragma unroll
    for (int j = 0; j < 8; j++)
#pragma unroll
        for (int x = 0; x < 4; x++) oacc[j][x] = 0.f;
    float mrow[2] = {-INFINITY, -INFINITY};
    float lrow[2] = {0.f, 0.f};

    const int ntile = SEQ / 64;   // 32
    ASTAGE(0, 0);

    for (int t = 0; t < ntile; t++) {
        const int bi = t & 1;
        if (t + 1 < ntile) { ASTAGE(t + 1, bi ^ 1); }
        else { CP_COMMIT(); }
        CP_WAIT(1);
        __syncthreads();

        const uint32_t ksb = smb + (uint32_t)((KOFF(bi) + loffT) * 2);
        const uint32_t vsb = smb + (uint32_t)((VOFF(bi) + loffT) * 2);

        float sacc[8][4];
#pragma unroll
        for (int j = 0; j < 8; j++)
            sacc[j][0] = sacc[j][1] = sacc[j][2] = sacc[j][3] = 0.f;
#pragma unroll
        for (int j2 = 0; j2 < 4; j2++) {
#pragma unroll
            for (int kk = 0; kk < 4; kk++) {
                unsigned b0, b1, b2, b3;
                ldsm_x4(b0, b1, b2, b3,
                        ksb + (uint32_t)((j2 * 16 * TKSTR + kk * 16) * 2));
                mma_f16(sacc[2 * j2],     qf[kk], b0, b1);
                mma_f16(sacc[2 * j2 + 1], qf[kk], b2, b3);
            }
        }

        float mA = sacc[0][0], mB = sacc[0][2];
#pragma unroll
        for (int j = 0; j < 8; j++) {
            mA = fmaxf(mA, fmaxf(sacc[j][0], sacc[j][1]));
            mB = fmaxf(mB, fmaxf(sacc[j][2], sacc[j][3]));
        }
        mA = fmaxf(mA, __shfl_xor_sync(0xffffffffu, mA, 1));
        mA = fmaxf(mA, __shfl_xor_sync(0xffffffffu, mA, 2));
        mB = fmaxf(mB, __shfl_xor_sync(0xffffffffu, mB, 1));
        mB = fmaxf(mB, __shfl_xor_sync(0xffffffffu, mB, 2));
        const float mnA = fmaxf(mrow[0], mA);
        const float mnB = fmaxf(mrow[1], mB);
        const float alA = exp2f(mrow[0] - mnA);
        const float alB = exp2f(mrow[1] - mnB);
        mrow[0] = mnA; mrow[1] = mnB;

        unsigned pA[8], pB[8];
        float sumA = 0.f, sumB = 0.f;
#pragma unroll
        for (int j = 0; j < 8; j++) {
            pA[j] = ex2_h2(sacc[j][0] - mnA, sacc[j][1] - mnA);
            pB[j] = ex2_h2(sacc[j][2] - mnB, sacc[j][3] - mnB);
            float2 fa = u32_to_f2(pA[j]);
            float2 fb = u32_to_f2(pB[j]);
            sumA += fa.x + fa.y;
            sumB += fb.x + fb.y;
        }
        sumA += __shfl_xor_sync(0xffffffffu, sumA, 1);
        sumA += __shfl_xor_sync(0xffffffffu, sumA, 2);
        sumB += __shfl_xor_sync(0xffffffffu, sumB, 1);
        sumB += __shfl_xor_sync(0xffffffffu, sumB, 2);
        lrow[0] = lrow[0] * alA + sumA;
        lrow[1] = lrow[1] * alB + sumB;

#pragma unroll
        for (int j = 0; j < 8; j++) {
            oacc[j][0] *= alA; oacc[j][1] *= alA;
            oacc[j][2] *= alB; oacc[j][3] *= alB;
        }

#pragma unroll
        for (int d2 = 0; d2 < 4; d2++) {
#pragma unroll
            for (int kk = 0; kk < 4; kk++) {
                unsigned b0, b1, b2, b3;
                ldsm_x4(b0, b1, b2, b3,
                        vsb + (uint32_t)((d2 * 16 * TKSTR + kk * 16) * 2));
                const unsigned af[4] = { pA[2 * kk], pB[2 * kk],
                                         pA[2 * kk + 1], pB[2 * kk + 1] };
                mma_f16(oacc[2 * d2],     af, b0, b1);
                mma_f16(oacc[2 * d2 + 1], af, b2, b3);
            }
        }
        __syncthreads();
    }

    const float invA = 1.f / lrow[0];
    const float invB = 1.f / lrow[1];
    const size_t tr = (size_t)b * SEQ + q0 + warp * 16 + r4;
    __half* ob = g_atth + tr * D_MODEL + h * HD;
#pragma unroll
    for (int j = 0; j < 8; j++) {
        const int cc = j * 8 + 2 * c4;
        *(__half2*)&ob[cc] = __floats2half2_rn(oacc[j][0] * invA, oacc[j][1] * invA);
        *(__half2*)&ob[8 * D_MODEL + cc] =
            __floats2half2_rn(oacc[j][2] * invB, oacc[j][3] * invB);
    }
#undef ASTAGE
}

// ---------------------------------------------------------------------------
extern "C" void kernel_launch(void* const* d_in, const int* in_sizes, int n_in,
                              void* d_out, int out_size)
{
    const float* x    = (const float*)d_in[0];
    const float* Wqkv = (const float*)d_in[1];
    const float* bqkv = (const float*)d_in[2];
    const float* Wout = (const float*)d_in[3];
    const float* bout = (const float*)d_in[4];
    float* out = (float*)d_out;

    __half *xh, *wqkvTh, *woutTh, *atth;
    cudaGetSymbolAddress((void**)&xh, g_xh);
    cudaGetSymbolAddress((void**)&wqkvTh, g_wqkvTh);
    cudaGetSymbolAddress((void**)&woutTh, g_woutTh);
    cudaGetSymbolAddress((void**)&atth, g_atth);

    cudaFuncSetAttribute(gemm_h_kernel,
                         cudaFuncAttributeMaxDynamicSharedMemorySize, GEMM_SMEM_BYTES);

    // 0) pre-passes
    cvt_h_kernel<<<296, 256>>>((const float4*)x, (uint4*)xh, NTOK * D_MODEL / 8);
    {
        dim3 blk(32, 8);
        transpose_cvt_kernel<<<dim3(QKV_LD / 32, D_MODEL / 32), blk>>>(
            Wqkv, wqkvTh, D_MODEL, QKV_LD);
        transpose_cvt_kernel<<<dim3(D_MODEL / 32, D_MODEL / 32), blk>>>(
            Wout, woutTh, D_MODEL, D_MODEL);
    }
    // 1) qkv projection
    {
        dim3 grid(QKV_LD / 128, NTOK / 128);   // (24, 32)
        gemm_h_kernel<<<grid, 128, GEMM_SMEM_BYTES>>>(
            xh, wqkvTh, bqkv, nullptr, NTOK, QKV_LD, D_MODEL, 1);
    }
    // 2) attention
    {
        dim3 grid(SEQ / 64, NHEAD, BATCH);     // (32, 16, 2)
        attn_h_kernel<<<grid, 128, ATT_SMEM_BYTES>>>();
    }
    // 3) output projection (fp32)
    {
        dim3 grid(D_MODEL / 128, NTOK / 128);  // (8, 32)
        gemm_h_kernel<<<grid, 128, GEMM_SMEM_BYTES>>>(
            atth, woutTh, bout, out, NTOK, D_MODEL, D_MODEL, 0);
    }
}

// round 14
// speedup vs baseline: 1.1167x; 1.1167x over previous
#include <cuda_runtime.h>
#include <cuda_fp16.h>
#include <math.h>
#include <stdint.h>

// Problem constants
#define D_MODEL 1024
#define NHEAD   16
#define HD      64
#define SEQ     2048
#define BATCH   2
#define NTOK    (BATCH * SEQ)          // 4096
#define QKV_LD  (3 * D_MODEL)          // 3072

// Q pre-scale: 1/sqrt(64) * log2(e)  (softmax done base-2)
#define QSCALE 0.18033688011112042f

// HBM scratch (no cudaMalloc allowed)
__device__ __half g_xh[(size_t)NTOK * D_MODEL];
__device__ __half g_wqkvTh[(size_t)QKV_LD * D_MODEL];
__device__ __half g_woutTh[(size_t)D_MODEL * D_MODEL];
__device__ __half g_qkvh[(size_t)NTOK * QKV_LD];          // Q(scaled)/K fp16
__device__ __half g_vt[(size_t)BATCH * NHEAD * HD * SEQ]; // V^T fp16 [bh][d][s]
__device__ __half g_atth[(size_t)NTOK * D_MODEL];

// ---------------------------------------------------------------------------
__device__ __forceinline__ uint32_t smem_u32(const void* p) {
    uint32_t a;
    asm("{ .reg .u64 t; cvta.to.shared.u64 t, %1; cvt.u32.u64 %0, t; }"
        : "=r"(a) : "l"(p));
    return a;
}
__device__ __forceinline__ unsigned h2_to_u32(__half2 h) {
    return *reinterpret_cast<unsigned*>(&h);
}
__device__ __forceinline__ float2 u32_to_f2(unsigned u) {
    __half2 h = *reinterpret_cast<__half2*>(&u);
    return __half22float2(h);
}
__device__ __forceinline__ void mma_f16(float c[4], const unsigned a[4],
                                        unsigned b0, unsigned b1) {
    asm volatile(
        "mma.sync.aligned.m16n8k16.row.col.f32.f16.f16.f32 "
        "{%0,%1,%2,%3}, {%4,%5,%6,%7}, {%8,%9}, {%0,%1,%2,%3};"
        : "+f"(c[0]), "+f"(c[1]), "+f"(c[2]), "+f"(c[3])
        : "r"(a[0]), "r"(a[1]), "r"(a[2]), "r"(a[3]), "r"(b0), "r"(b1));
}
__device__ __forceinline__ void ldsm_x4(unsigned& r0, unsigned& r1,
                                        unsigned& r2, unsigned& r3, uint32_t a) {
    asm volatile("ldmatrix.sync.aligned.m8n8.x4.shared.b16 {%0,%1,%2,%3}, [%4];"
                 : "=r"(r0), "=r"(r1), "=r"(r2), "=r"(r3) : "r"(a));
}
__device__ __forceinline__ unsigned ex2_h2(float lo, float hi) {
    unsigned r;
    asm("{\n\t.reg .b32 t;\n\tcvt.rn.f16x2.f32 t, %2, %1;\n\t"
        "ex2.approx.f16x2 %0, t;\n\t}"
        : "=r"(r) : "f"(lo), "f"(hi));
    return r;
}
#define CP16(dst, src) \
    asm volatile("cp.async.cg.shared.global [%0], [%1], 16;" \
                 :: "r"(dst), "l"(src) : "memory")
#define CP_COMMIT() asm volatile("cp.async.commit_group;" ::: "memory")
#define CP_WAIT(n)  asm volatile("cp.async.wait_group %0;" :: "n"(n) : "memory")

// ---------------------------------------------------------------------------
// Pre-passes
// ---------------------------------------------------------------------------
__global__ __launch_bounds__(256) void cvt_h_kernel(
    const float4* __restrict__ src, uint4* __restrict__ dst, int n8)
{
    for (int i = blockIdx.x * 256 + threadIdx.x; i < n8; i += gridDim.x * 256) {
        float4 a = src[2 * i], b = src[2 * i + 1];
        uint4 o;
        o.x = h2_to_u32(__floats2half2_rn(a.x, a.y));
        o.y = h2_to_u32(__floats2half2_rn(a.z, a.w));
        o.z = h2_to_u32(__floats2half2_rn(b.x, b.y));
        o.w = h2_to_u32(__floats2half2_rn(b.z, b.w));
        dst[i] = o;
    }
}

__global__ void transpose_cvt_kernel(
    const float* __restrict__ in, __half* __restrict__ out, int R, int C)
{
    __shared__ float t[32][33];
    const int bx = blockIdx.x * 32;
    const int by = blockIdx.y * 32;
    const int x = threadIdx.x, y = threadIdx.y;
#pragma unroll
    for (int j = 0; j < 32; j += 8)
        t[y + j][x] = in[(size_t)(by + y + j) * C + bx + x];
    __syncthreads();
#pragma unroll
    for (int j = 0; j < 32; j += 8)
        out[(size_t)(bx + y + j) * R + by + x] = __float2half(t[x][y + j]);
}

// ---------------------------------------------------------------------------
// FP16 mma GEMM (R7 configuration, verbatim): CTA 128x128, 4 warps of 64x64,
// cp.async 4-stage, K-chunk 32, LDSM fragment loads, stride 40 half.
// mode 0: fp32 out.  mode 1: qkv (Q scaled by QSCALE, K fp16, V -> g_vt).
// ---------------------------------------------------------------------------
#define HSTR 40
#define A_ST_H (128 * HSTR)              // 5120 half
#define STG_H  (2 * A_ST_H)              // 10240 half per stage
#define GEMM_SMEM_BYTES (4 * STG_H * 2)  // 81920

__global__ __launch_bounds__(128, 2) void gemm_h_kernel(
    const __half* __restrict__ A, const __half* __restrict__ Bt,
    const float* __restrict__ bias, void* __restrict__ Cout,
    int M, int N, int K, int mode)
{
    extern __shared__ __half smh[];
    const uint32_t smb = smem_u32(smh);

    const int tid  = threadIdx.x;
    const int lane = tid & 31;
    const int warp = tid >> 5;
    const int r4 = lane >> 2;
    const int c4 = lane & 3;
    const int wrow = (warp >> 1) * 64;
    const int wcol = (warp & 1) * 64;
    const int row0 = blockIdx.y * 128;
    const int col0 = blockIdx.x * 128;

    const __half* Ablk = A  + (size_t)row0 * K;
    const __half* Bblk = Bt + (size_t)col0 * K;

    const uint32_t loffA = (uint32_t)((lane & 15) * HSTR + (lane >> 4) * 8);
    const uint32_t loffB = (uint32_t)(((lane >> 4) * 8 + (lane & 7)) * HSTR
                                      + ((lane >> 3) & 1) * 8);

#define GSTAGE(c, st) do {                                                   \
        const __half* Ag = Ablk + (c) * 32;                                  \
        const __half* Bg = Bblk + (c) * 32;                                  \
        _Pragma("unroll")                                                    \
        for (int i = 0; i < 4; i++) {                                        \
            const int id = tid + 128 * i;                                    \
            const int r = id >> 2, ch = id & 3;                              \
            CP16(smb + (uint32_t)(((st) * STG_H + r * HSTR + ch * 8) * 2),   \
                 Ag + (size_t)r * K + ch * 8);                               \
            CP16(smb + (uint32_t)(((st) * STG_H + A_ST_H + r * HSTR + ch * 8) * 2), \
                 Bg + (size_t)r * K + ch * 8);                               \
        }                                                                    \
        CP_COMMIT();                                                         \
    } while (0)

    float acc[4][8][4];
#pragma unroll
    for (int mf = 0; mf < 4; mf++)
#pragma unroll
        for (int nf = 0; nf < 8; nf++)
#pragma unroll
            for (int x = 0; x < 4; x++) acc[mf][nf][x] = 0.f;

    const int nchunk = K / 32;
    GSTAGE(0, 0);
    GSTAGE(1, 1);
    GSTAGE(2, 2);

    for (int c = 0; c < nchunk; c++) {
        CP_WAIT(2);
        __syncthreads();

        const uint32_t stA = smb + (uint32_t)(((c & 3) * STG_H) * 2);
        const uint32_t stB = stA + (uint32_t)(A_ST_H * 2);

#pragma unroll
        for (int ks = 0; ks < 2; ks++) {
            unsigned af[4][4];
            const uint32_t aB = stA + (uint32_t)((wrow * HSTR + ks * 16 + loffA) * 2);
#pragma unroll
            for (int mf = 0; mf < 4; mf++)
                ldsm_x4(af[mf][0], af[mf][1], af[mf][2], af[mf][3],
                        aB + (uint32_t)(mf * 16 * HSTR * 2));
            unsigned bf0[8], bf1[8];
            const uint32_t bB = stB + (uint32_t)((wcol * HSTR + ks * 16 + loffB) * 2);
#pragma unroll
            for (int np = 0; np < 4; np++) {
                unsigned r0, r1, r2, r3;
                ldsm_x4(r0, r1, r2, r3, bB + (uint32_t)(np * 16 * HSTR * 2));
                bf0[2 * np] = r0; bf1[2 * np] = r1;
                bf0[2 * np + 1] = r2; bf1[2 * np + 1] = r3;
            }
#pragma unroll
            for (int nf = 0; nf < 8; nf++)
#pragma unroll
                for (int mf = 0; mf < 4; mf++)
                    mma_f16(acc[mf][nf], af[mf], bf0[nf], bf1[nf]);
        }

        if (c + 3 < nchunk) { GSTAGE(c + 3, (c + 3) & 3); }
        else { CP_COMMIT(); }
    }

    // ---- epilogue ----
    if (mode == 0) {
        float* C = (float*)Cout;
#pragma unroll
        for (int mf = 0; mf < 4; mf++) {
            const int r = row0 + wrow + mf * 16 + r4;
#pragma unroll
            for (int nf = 0; nf < 8; nf++) {
                const int cc = col0 + wcol + nf * 8 + 2 * c4;
                const float bx = bias[cc], by = bias[cc + 1];
                *(float2*)&C[(size_t)r * N + cc] =
                    make_float2(acc[mf][nf][0] + bx, acc[mf][nf][1] + by);
                *(float2*)&C[(size_t)(r + 8) * N + cc] =
                    make_float2(acc[mf][nf][2] + bx, acc[mf][nf][3] + by);
            }
        }
    } else {
        const int cb  = col0 + wcol;
        const int h   = cb / 192;
        const int sec = (cb % 192) / 64;
        if (sec < 2) {
            const float sc = (sec == 0) ? QSCALE : 1.0f;
#pragma unroll
            for (int mf = 0; mf < 4; mf++) {
                const int r = row0 + wrow + mf * 16 + r4;
#pragma unroll
                for (int nf = 0; nf < 8; nf++) {
                    const int cc = cb + nf * 8 + 2 * c4;
                    const float bx = bias[cc], by = bias[cc + 1];
                    __half2 v0 = __floats2half2_rn((acc[mf][nf][0] + bx) * sc,
                                                   (acc[mf][nf][1] + by) * sc);
                    __half2 v1 = __floats2half2_rn((acc[mf][nf][2] + bx) * sc,
                                                   (acc[mf][nf][3] + by) * sc);
                    *(__half2*)&g_qkvh[(size_t)r * QKV_LD + cc] = v0;
                    *(__half2*)&g_qkvh[(size_t)(r + 8) * QKV_LD + cc] = v1;
                }
            }
        } else {
#pragma unroll
            for (int mf = 0; mf < 4; mf++) {
                const int r = row0 + wrow + mf * 16 + r4;
                const int bb = r >> 11, s = r & 2047;
                const int bb8 = (r + 8) >> 11, s8 = (r + 8) & 2047;
#pragma unroll
                for (int nf = 0; nf < 8; nf++) {
                    const int cc = cb + nf * 8 + 2 * c4;
                    const int d = (cc % 192) - 128;
                    const float bx = bias[cc], by = bias[cc + 1];
                    __half* v0 = g_vt + ((size_t)(bb * NHEAD + h) * HD + d) * SEQ;
                    v0[s]        = __float2half(acc[mf][nf][0] + bx);
                    v0[SEQ + s]  = __float2half(acc[mf][nf][1] + by);
                    __half* v8 = g_vt + ((size_t)(bb8 * NHEAD + h) * HD + d) * SEQ;
                    v8[s8]       = __float2half(acc[mf][nf][2] + bx);
                    v8[SEQ + s8] = __float2half(acc[mf][nf][3] + by);
                }
            }
        }
    }
#undef GSTAGE
}

// ---------------------------------------------------------------------------
// FlashAttention fp16 mma: identical compute to R7 (bit-identical numerics),
// but K/V staged in 128-key double buffers processed as two 64-key halves:
// half the CP_WAIT/__syncthreads/commit windows.
// K tile: 128 rows x 64 d, stride 72.  V tile: 64 d x 128 s, stride 136.
// smem: 2 * (128*72 + 64*136) half = 35840 half = 71680 B -> 3 CTAs/SM.
// ---------------------------------------------------------------------------
#define TKSTR 72
#define TVSTR 136
#define BUFH  (128 * TKSTR + 64 * TVSTR)   // 17920 half per buffer
#define KOFF(bi) ((bi) * BUFH)
#define VOFF(bi) ((bi) * BUFH + 128 * TKSTR)
#define ATT_SMEM_BYTES (2 * BUFH * 2)      // 71680

__global__ __launch_bounds__(128, 3) void attn_h_kernel()
{
    extern __shared__ __half smh[];
    const uint32_t smb = smem_u32(smh);
    const int tid  = threadIdx.x;
    const int lane = tid & 31;
    const int warp = tid >> 5;
    const int b  = blockIdx.z;
    const int h  = blockIdx.y;
    const int q0 = blockIdx.x * 64;
    const int r4 = lane >> 2;
    const int c4 = lane & 3;

    const uint32_t loffK = (uint32_t)(((lane >> 4) * 8 + (lane & 7)) * TKSTR
                                      + ((lane >> 3) & 1) * 8);
    const uint32_t loffV = (uint32_t)(((lane >> 4) * 8 + (lane & 7)) * TVSTR
                                      + ((lane >> 3) & 1) * 8);

    unsigned qf[4][4];
    {
        const __half* qr  = g_qkvh + (size_t)(b * SEQ + q0 + warp * 16 + r4) * QKV_LD + h * 192;
        const __half* qr8 = qr + (size_t)8 * QKV_LD;
#pragma unroll
        for (int kk = 0; kk < 4; kk++) {
            const int k0 = kk * 16 + 2 * c4;
            qf[kk][0] = *(const unsigned*)(qr + k0);
            qf[kk][1] = *(const unsigned*)(qr8 + k0);
            qf[kk][2] = *(const unsigned*)(qr + k0 + 8);
            qf[kk][3] = *(const unsigned*)(qr8 + k0 + 8);
        }
    }

    const __half* Kg = g_qkvh + (size_t)b * SEQ * QKV_LD + h * 192 + 64;
    const __half* Vg = g_vt + (size_t)(b * NHEAD + h) * HD * SEQ;

    // stage = 128 keys: K 128 rows x 8 float4; V 64 rows x 16 float4
#define ASTAGE(t, bi) do {                                                   \
        const __half* Kt = Kg + (size_t)(t) * 128 * QKV_LD;                  \
        const __half* Vt = Vg + (t) * 128;                                   \
        _Pragma("unroll")                                                    \
        for (int i = 0; i < 8; i++) {                                        \
            const int id = tid + 128 * i;                                    \
            const int rk = id >> 3, chk = id & 7;                            \
            CP16(smb + (uint32_t)((KOFF(bi) + rk * TKSTR + chk * 8) * 2),    \
                 Kt + (size_t)rk * QKV_LD + chk * 8);                        \
            const int rv = id >> 4, chv = id & 15;                           \
            CP16(smb + (uint32_t)((VOFF(bi) + rv * TVSTR + chv * 8) * 2),    \
                 Vt + (size_t)rv * SEQ + chv * 8);                           \
        }                                                                    \
        CP_COMMIT();                                                         \
    } while (0)

    float oacc[8][4];
#pragma unroll
    for (int j = 0; j < 8; j++)
#pragma unroll
        for (int x = 0; x < 4; x++) oacc[j][x] = 0.f;
    float mrow[2] = {-INFINITY, -INFINITY};
    float lrow[2] = {0.f, 0.f};

    const int ntile = SEQ / 128;   // 16
    ASTAGE(0, 0);

    for (int t = 0; t < ntile; t++) {
        const int bi = t & 1;
        if (t + 1 < ntile) { ASTAGE(t + 1, bi ^ 1); }
        else { CP_COMMIT(); }
        CP_WAIT(1);
        __syncthreads();

#pragma unroll
        for (int hf = 0; hf < 2; hf++) {
            const uint32_t ksb = smb + (uint32_t)((KOFF(bi) + hf * 64 * TKSTR + loffK) * 2);
            const uint32_t vsb = smb + (uint32_t)((VOFF(bi) + hf * 64 + loffV) * 2);

            float sacc[8][4];
#pragma unroll
            for (int j = 0; j < 8; j++)
                sacc[j][0] = sacc[j][1] = sacc[j][2] = sacc[j][3] = 0.f;
#pragma unroll
            for (int j2 = 0; j2 < 4; j2++) {
#pragma unroll
                for (int kk = 0; kk < 4; kk++) {
                    unsigned b0, b1, b2, b3;
                    ldsm_x4(b0, b1, b2, b3,
                            ksb + (uint32_t)((j2 * 16 * TKSTR + kk * 16) * 2));
                    mma_f16(sacc[2 * j2],     qf[kk], b0, b1);
                    mma_f16(sacc[2 * j2 + 1], qf[kk], b2, b3);
                }
            }

            float mA = sacc[0][0], mB = sacc[0][2];
#pragma unroll
            for (int j = 0; j < 8; j++) {
                mA = fmaxf(mA, fmaxf(sacc[j][0], sacc[j][1]));
                mB = fmaxf(mB, fmaxf(sacc[j][2], sacc[j][3]));
            }
            mA = fmaxf(mA, __shfl_xor_sync(0xffffffffu, mA, 1));
            mA = fmaxf(mA, __shfl_xor_sync(0xffffffffu, mA, 2));
            mB = fmaxf(mB, __shfl_xor_sync(0xffffffffu, mB, 1));
            mB = fmaxf(mB, __shfl_xor_sync(0xffffffffu, mB, 2));
            const float mnA = fmaxf(mrow[0], mA);
            const float mnB = fmaxf(mrow[1], mB);
            const float alA = exp2f(mrow[0] - mnA);
            const float alB = exp2f(mrow[1] - mnB);
            mrow[0] = mnA; mrow[1] = mnB;

            unsigned pA[8], pB[8];
            float sumA = 0.f, sumB = 0.f;
#pragma unroll
            for (int j = 0; j < 8; j++) {
                pA[j] = ex2_h2(sacc[j][0] - mnA, sacc[j][1] - mnA);
                pB[j] = ex2_h2(sacc[j][2] - mnB, sacc[j][3] - mnB);
                float2 fa = u32_to_f2(pA[j]);
                float2 fb = u32_to_f2(pB[j]);
                sumA += fa.x + fa.y;
                sumB += fb.x + fb.y;
            }
            sumA += __shfl_xor_sync(0xffffffffu, sumA, 1);
            sumA += __shfl_xor_sync(0xffffffffu, sumA, 2);
            sumB += __shfl_xor_sync(0xffffffffu, sumB, 1);
            sumB += __shfl_xor_sync(0xffffffffu, sumB, 2);
            lrow[0] = lrow[0] * alA + sumA;
            lrow[1] = lrow[1] * alB + sumB;

#pragma unroll
            for (int j = 0; j < 8; j++) {
                oacc[j][0] *= alA; oacc[j][1] *= alA;
                oacc[j][2] *= alB; oacc[j][3] *= alB;
            }

#pragma unroll
            for (int d2 = 0; d2 < 4; d2++) {
#pragma unroll
                for (int kk = 0; kk < 4; kk++) {
                    unsigned b0, b1, b2, b3;
                    ldsm_x4(b0, b1, b2, b3,
                            vsb + (uint32_t)((d2 * 16 * TVSTR + kk * 16) * 2));
                    const unsigned af[4] = { pA[2 * kk], pB[2 * kk],
                                             pA[2 * kk + 1], pB[2 * kk + 1] };
                    mma_f16(oacc[2 * d2],     af, b0, b1);
                    mma_f16(oacc[2 * d2 + 1], af, b2, b3);
                }
            }
        }
        __syncthreads();
    }

    const float invA = 1.f / lrow[0];
    const float invB = 1.f / lrow[1];
    const size_t tr = (size_t)b * SEQ + q0 + warp * 16 + r4;
    __half* ob = g_atth + tr * D_MODEL + h * HD;
#pragma unroll
    for (int j = 0; j < 8; j++) {
        const int cc = j * 8 + 2 * c4;
        *(__half2*)&ob[cc] = __floats2half2_rn(oacc[j][0] * invA, oacc[j][1] * invA);
        *(__half2*)&ob[8 * D_MODEL + cc] =
            __floats2half2_rn(oacc[j][2] * invB, oacc[j][3] * invB);
    }
#undef ASTAGE
}

// ---------------------------------------------------------------------------
extern "C" void kernel_launch(void* const* d_in, const int* in_sizes, int n_in,
                              void* d_out, int out_size)
{
    const float* x    = (const float*)d_in[0];
    const float* Wqkv = (const float*)d_in[1];
    const float* bqkv = (const float*)d_in[2];
    const float* Wout = (const float*)d_in[3];
    const float* bout = (const float*)d_in[4];
    float* out = (float*)d_out;

    __half *xh, *wqkvTh, *woutTh, *atth;
    cudaGetSymbolAddress((void**)&xh, g_xh);
    cudaGetSymbolAddress((void**)&wqkvTh, g_wqkvTh);
    cudaGetSymbolAddress((void**)&woutTh, g_woutTh);
    cudaGetSymbolAddress((void**)&atth, g_atth);

    cudaFuncSetAttribute(gemm_h_kernel,
                         cudaFuncAttributeMaxDynamicSharedMemorySize, GEMM_SMEM_BYTES);
    cudaFuncSetAttribute(attn_h_kernel,
                         cudaFuncAttributeMaxDynamicSharedMemorySize, ATT_SMEM_BYTES);

    // 0) pre-passes
    cvt_h_kernel<<<296, 256>>>((const float4*)x, (uint4*)xh, NTOK * D_MODEL / 8);
    {
        dim3 blk(32, 8);
        transpose_cvt_kernel<<<dim3(QKV_LD / 32, D_MODEL / 32), blk>>>(
            Wqkv, wqkvTh, D_MODEL, QKV_LD);
        transpose_cvt_kernel<<<dim3(D_MODEL / 32, D_MODEL / 32), blk>>>(
            Wout, woutTh, D_MODEL, D_MODEL);
    }
    // 1) qkv projection
    {
        dim3 grid(QKV_LD / 128, NTOK / 128);   // (24, 32)
        gemm_h_kernel<<<grid, 128, GEMM_SMEM_BYTES>>>(
            xh, wqkvTh, bqkv, nullptr, NTOK, QKV_LD, D_MODEL, 1);
    }
    // 2) attention
    {
        dim3 grid(SEQ / 64, NHEAD, BATCH);     // (32, 16, 2)
        attn_h_kernel<<<grid, 128, ATT_SMEM_BYTES>>>();
    }
    // 3) output projection (fp32)
    {
        dim3 grid(D_MODEL / 128, NTOK / 128);  // (8, 32)
        gemm_h_kernel<<<grid, 128, GEMM_SMEM_BYTES>>>(
            atth, woutTh, bout, out, NTOK, D_MODEL, D_MODEL, 0);
    }
}

// round 15
// speedup vs baseline: 1.1428x; 1.0234x over previous
#include <cuda_runtime.h>
#include <cuda_fp16.h>
#include <math.h>
#include <stdint.h>

// Problem constants
#define D_MODEL 1024
#define NHEAD   16
#define HD      64
#define SEQ     2048
#define BATCH   2
#define NTOK    (BATCH * SEQ)          // 4096
#define QKV_LD  (3 * D_MODEL)          // 3072

// Q pre-scale: 1/sqrt(64) * log2(e)  (softmax done base-2)
#define QSCALE 0.18033688011112042f

// HBM scratch (no cudaMalloc allowed)
__device__ __half g_xh[(size_t)NTOK * D_MODEL];
__device__ __half g_wqkvh[(size_t)D_MODEL * QKV_LD];      // Wqkv fp16 [K][N] (no transpose)
__device__ __half g_wouth[(size_t)D_MODEL * D_MODEL];     // Wout fp16 [K][N]
__device__ __half g_qkvh[(size_t)NTOK * QKV_LD];          // Q(scaled)/K fp16
__device__ __half g_vt[(size_t)BATCH * NHEAD * HD * SEQ]; // V^T fp16 [bh][d][s]
__device__ __half g_atth[(size_t)NTOK * D_MODEL];

// ---------------------------------------------------------------------------
__device__ __forceinline__ uint32_t smem_u32(const void* p) {
    uint32_t a;
    asm("{ .reg .u64 t; cvta.to.shared.u64 t, %1; cvt.u32.u64 %0, t; }"
        : "=r"(a) : "l"(p));
    return a;
}
__device__ __forceinline__ unsigned h2_to_u32(__half2 h) {
    return *reinterpret_cast<unsigned*>(&h);
}
__device__ __forceinline__ float2 u32_to_f2(unsigned u) {
    __half2 h = *reinterpret_cast<__half2*>(&u);
    return __half22float2(h);
}
__device__ __forceinline__ void mma_f16(float c[4], const unsigned a[4],
                                        unsigned b0, unsigned b1) {
    asm volatile(
        "mma.sync.aligned.m16n8k16.row.col.f32.f16.f16.f32 "
        "{%0,%1,%2,%3}, {%4,%5,%6,%7}, {%8,%9}, {%0,%1,%2,%3};"
        : "+f"(c[0]), "+f"(c[1]), "+f"(c[2]), "+f"(c[3])
        : "r"(a[0]), "r"(a[1]), "r"(a[2]), "r"(a[3]), "r"(b0), "r"(b1));
}
__device__ __forceinline__ void ldsm_x4(unsigned& r0, unsigned& r1,
                                        unsigned& r2, unsigned& r3, uint32_t a) {
    asm volatile("ldmatrix.sync.aligned.m8n8.x4.shared.b16 {%0,%1,%2,%3}, [%4];"
                 : "=r"(r0), "=r"(r1), "=r"(r2), "=r"(r3) : "r"(a));
}
__device__ __forceinline__ void ldsm_x4_t(unsigned& r0, unsigned& r1,
                                          unsigned& r2, unsigned& r3, uint32_t a) {
    asm volatile("ldmatrix.sync.aligned.m8n8.x4.trans.shared.b16 {%0,%1,%2,%3}, [%4];"
                 : "=r"(r0), "=r"(r1), "=r"(r2), "=r"(r3) : "r"(a));
}
__device__ __forceinline__ unsigned ex2_h2(float lo, float hi) {
    unsigned r;
    asm("{\n\t.reg .b32 t;\n\tcvt.rn.f16x2.f32 t, %2, %1;\n\t"
        "ex2.approx.f16x2 %0, t;\n\t}"
        : "=r"(r) : "f"(lo), "f"(hi));
    return r;
}
#define CP16(dst, src) \
    asm volatile("cp.async.cg.shared.global [%0], [%1], 16;" \
                 :: "r"(dst), "l"(src) : "memory")
#define CP_COMMIT() asm volatile("cp.async.commit_group;" ::: "memory")
#define CP_WAIT(n)  asm volatile("cp.async.wait_group %0;" :: "n"(n) : "memory")

// ---------------------------------------------------------------------------
// Pre-pass: pure elementwise fp32 -> fp16 (no transpose needed anymore)
// ---------------------------------------------------------------------------
__global__ __launch_bounds__(256) void cvt_h_kernel(
    const float4* __restrict__ src, uint4* __restrict__ dst, int n8)
{
    for (int i = blockIdx.x * 256 + threadIdx.x; i < n8; i += gridDim.x * 256) {
        float4 a = src[2 * i], b = src[2 * i + 1];
        uint4 o;
        o.x = h2_to_u32(__floats2half2_rn(a.x, a.y));
        o.y = h2_to_u32(__floats2half2_rn(a.z, a.w));
        o.z = h2_to_u32(__floats2half2_rn(b.x, b.y));
        o.w = h2_to_u32(__floats2half2_rn(b.z, b.w));
        dst[i] = o;
    }
}

// ---------------------------------------------------------------------------
// FP16 mma GEMM (R7 compute, B now from row-major W[K][N] via ldmatrix.trans):
// CTA 128x128, 4 warps of 64x64, cp.async 4-stage, K-chunk 32.
// As [m][k] stride 40; Bs [k][n] stride 136 (272 B rows -> LDSM phase-distinct).
// mode 0: fp32 out.  mode 1: qkv (Q scaled by QSCALE, K fp16, V -> g_vt).
// ---------------------------------------------------------------------------
#define HSTR 40
#define BSTR 136
#define A_ST_H (128 * HSTR)              // 5120 half
#define B_ST_H (32 * BSTR)               // 4352 half
#define STG_H  (A_ST_H + B_ST_H)         // 9472 half per stage
#define GEMM_SMEM_BYTES (4 * STG_H * 2)  // 75776

__global__ __launch_bounds__(128, 2) void gemm_h_kernel(
    const __half* __restrict__ A, const __half* __restrict__ B,
    const float* __restrict__ bias, void* __restrict__ Cout,
    int M, int N, int K, int mode)
{
    extern __shared__ __half smh[];
    const uint32_t smb = smem_u32(smh);

    const int tid  = threadIdx.x;
    const int lane = tid & 31;
    const int warp = tid >> 5;
    const int r4 = lane >> 2;
    const int c4 = lane & 3;
    const int wrow = (warp >> 1) * 64;
    const int wcol = (warp & 1) * 64;
    const int row0 = blockIdx.y * 128;
    const int col0 = blockIdx.x * 128;

    const __half* Ablk = A + (size_t)row0 * K;
    const __half* Bblk = B + col0;

    // LDSM lane offsets (half units)
    const uint32_t loffA = (uint32_t)((lane & 15) * HSTR + (lane >> 4) * 8);
    const uint32_t loffB = (uint32_t)((lane & 15) * BSTR + (lane >> 4) * 8);

#define GSTAGE(c, st) do {                                                   \
        const __half* Ag = Ablk + (c) * 32;                                  \
        const __half* Bg = Bblk + (size_t)((c) * 32) * N;                    \
        _Pragma("unroll")                                                    \
        for (int i = 0; i < 4; i++) {                                        \
            const int id = tid + 128 * i;                                    \
            const int r = id >> 2, ch = id & 3;                              \
            CP16(smb + (uint32_t)(((st) * STG_H + r * HSTR + ch * 8) * 2),   \
                 Ag + (size_t)r * K + ch * 8);                               \
            const int rk = id >> 4, chb = id & 15;                           \
            CP16(smb + (uint32_t)(((st) * STG_H + A_ST_H + rk * BSTR + chb * 8) * 2), \
                 Bg + (size_t)rk * N + chb * 8);                             \
        }                                                                    \
        CP_COMMIT();                                                         \
    } while (0)

    float acc[4][8][4];
#pragma unroll
    for (int mf = 0; mf < 4; mf++)
#pragma unroll
        for (int nf = 0; nf < 8; nf++)
#pragma unroll
            for (int x = 0; x < 4; x++) acc[mf][nf][x] = 0.f;

    const int nchunk = K / 32;
    GSTAGE(0, 0);
    GSTAGE(1, 1);
    GSTAGE(2, 2);

    for (int c = 0; c < nchunk; c++) {
        CP_WAIT(2);
        __syncthreads();

        const uint32_t stA = smb + (uint32_t)(((c & 3) * STG_H) * 2);
        const uint32_t stB = stA + (uint32_t)(A_ST_H * 2);

#pragma unroll
        for (int ks = 0; ks < 2; ks++) {
            unsigned af[4][4];
            const uint32_t aB = stA + (uint32_t)((wrow * HSTR + ks * 16 + loffA) * 2);
#pragma unroll
            for (int mf = 0; mf < 4; mf++)
                ldsm_x4(af[mf][0], af[mf][1], af[mf][2], af[mf][3],
                        aB + (uint32_t)(mf * 16 * HSTR * 2));
            unsigned bf0[8], bf1[8];
            const uint32_t bB = stB + (uint32_t)((ks * 16 * BSTR + wcol + loffB) * 2);
#pragma unroll
            for (int np = 0; np < 4; np++) {
                unsigned r0, r1, r2, r3;
                ldsm_x4_t(r0, r1, r2, r3, bB + (uint32_t)(np * 16 * 2));
                bf0[2 * np] = r0; bf1[2 * np] = r1;
                bf0[2 * np + 1] = r2; bf1[2 * np + 1] = r3;
            }
#pragma unroll
            for (int nf = 0; nf < 8; nf++)
#pragma unroll
                for (int mf = 0; mf < 4; mf++)
                    mma_f16(acc[mf][nf], af[mf], bf0[nf], bf1[nf]);
        }

        if (c + 3 < nchunk) { GSTAGE(c + 3, (c + 3) & 3); }
        else { CP_COMMIT(); }
    }

    // ---- epilogue ----
    if (mode == 0) {
        float* C = (float*)Cout;
#pragma unroll
        for (int mf = 0; mf < 4; mf++) {
            const int r = row0 + wrow + mf * 16 + r4;
#pragma unroll
            for (int nf = 0; nf < 8; nf++) {
                const int cc = col0 + wcol + nf * 8 + 2 * c4;
                const float bx = bias[cc], by = bias[cc + 1];
                *(float2*)&C[(size_t)r * N + cc] =
                    make_float2(acc[mf][nf][0] + bx, acc[mf][nf][1] + by);
                *(float2*)&C[(size_t)(r + 8) * N + cc] =
                    make_float2(acc[mf][nf][2] + bx, acc[mf][nf][3] + by);
            }
        }
    } else {
        const int cb  = col0 + wcol;
        const int h   = cb / 192;
        const int sec = (cb % 192) / 64;
        if (sec < 2) {
            const float sc = (sec == 0) ? QSCALE : 1.0f;
#pragma unroll
            for (int mf = 0; mf < 4; mf++) {
                const int r = row0 + wrow + mf * 16 + r4;
#pragma unroll
                for (int nf = 0; nf < 8; nf++) {
                    const int cc = cb + nf * 8 + 2 * c4;
                    const float bx = bias[cc], by = bias[cc + 1];
                    __half2 v0 = __floats2half2_rn((acc[mf][nf][0] + bx) * sc,
                                                   (acc[mf][nf][1] + by) * sc);
                    __half2 v1 = __floats2half2_rn((acc[mf][nf][2] + bx) * sc,
                                                   (acc[mf][nf][3] + by) * sc);
                    *(__half2*)&g_qkvh[(size_t)r * QKV_LD + cc] = v0;
                    *(__half2*)&g_qkvh[(size_t)(r + 8) * QKV_LD + cc] = v1;
                }
            }
        } else {
#pragma unroll
            for (int mf = 0; mf < 4; mf++) {
                const int r = row0 + wrow + mf * 16 + r4;
                const int bb = r >> 11, s = r & 2047;
                const int bb8 = (r + 8) >> 11, s8 = (r + 8) & 2047;
#pragma unroll
                for (int nf = 0; nf < 8; nf++) {
                    const int cc = cb + nf * 8 + 2 * c4;
                    const int d = (cc % 192) - 128;
                    const float bx = bias[cc], by = bias[cc + 1];
                    __half* v0 = g_vt + ((size_t)(bb * NHEAD + h) * HD + d) * SEQ;
                    v0[s]        = __float2half(acc[mf][nf][0] + bx);
                    v0[SEQ + s]  = __float2half(acc[mf][nf][1] + by);
                    __half* v8 = g_vt + ((size_t)(bb8 * NHEAD + h) * HD + d) * SEQ;
                    v8[s8]       = __float2half(acc[mf][nf][2] + bx);
                    v8[SEQ + s8] = __float2half(acc[mf][nf][3] + by);
                }
            }
        }
    }
#undef GSTAGE
}

// ---------------------------------------------------------------------------
// FlashAttention fp16 mma (R7 best, verbatim): P in registers,
// base-2 softmax via ex2.approx.f16x2, LDSM K/V frags, cp.async dbl-buffer.
// 4 warps x 16 q = 64 q/CTA, 64-key tiles.
// ---------------------------------------------------------------------------
#define TKSTR 72
#define KOFF(bi) ((bi) * 4608)
#define VOFF(bi) (9216 + (bi) * 4608)
#define ATT_SMEM_BYTES (18432 * 2)

__global__ __launch_bounds__(128, 3) void attn_h_kernel()
{
    extern __shared__ __half smh[];
    const uint32_t smb = smem_u32(smh);
    const int tid  = threadIdx.x;
    const int lane = tid & 31;
    const int warp = tid >> 5;
    const int b  = blockIdx.z;
    const int h  = blockIdx.y;
    const int q0 = blockIdx.x * 64;
    const int r4 = lane >> 2;
    const int c4 = lane & 3;

    const uint32_t loffT = (uint32_t)(((lane >> 4) * 8 + (lane & 7)) * TKSTR
                                      + ((lane >> 3) & 1) * 8);

    unsigned qf[4][4];
    {
        const __half* qr  = g_qkvh + (size_t)(b * SEQ + q0 + warp * 16 + r4) * QKV_LD + h * 192;
        const __half* qr8 = qr + (size_t)8 * QKV_LD;
#pragma unroll
        for (int kk = 0; kk < 4; kk++) {
            const int k0 = kk * 16 + 2 * c4;
            qf[kk][0] = *(const unsigned*)(qr + k0);
            qf[kk][1] = *(const unsigned*)(qr8 + k0);
            qf[kk][2] = *(const unsigned*)(qr + k0 + 8);
            qf[kk][3] = *(const unsigned*)(qr8 + k0 + 8);
        }
    }

    const __half* Kg = g_qkvh + (size_t)b * SEQ * QKV_LD + h * 192 + 64;
    const __half* Vg = g_vt + (size_t)(b * NHEAD + h) * HD * SEQ;

#define ASTAGE(t, bi) do {                                                   \
        const __half* Kt = Kg + (size_t)(t) * 64 * QKV_LD;                   \
        const __half* Vt = Vg + (t) * 64;                                    \
        _Pragma("unroll")                                                    \
        for (int i = 0; i < 4; i++) {                                        \
            const int id = tid + 128 * i;                                    \
            const int r = id >> 3, ch = id & 7;                              \
            CP16(smb + (uint32_t)((KOFF(bi) + r * TKSTR + ch * 8) * 2),      \
                 Kt + (size_t)r * QKV_LD + ch * 8);                          \
            CP16(smb + (uint32_t)((VOFF(bi) + r * TKSTR + ch * 8) * 2),      \
                 Vt + (size_t)r * SEQ + ch * 8);                             \
        }                                                                    \
        CP_COMMIT();                                                         \
    } while (0)

    float oacc[8][4];
#pragma unroll
    for (int j = 0; j < 8; j++)
#pragma unroll
        for (int x = 0; x < 4; x++) oacc[j][x] = 0.f;
    float mrow[2] = {-INFINITY, -INFINITY};
    float lrow[2] = {0.f, 0.f};

    const int ntile = SEQ / 64;   // 32
    ASTAGE(0, 0);

    for (int t = 0; t < ntile; t++) {
        const int bi = t & 1;
        if (t + 1 < ntile) { ASTAGE(t + 1, bi ^ 1); }
        else { CP_COMMIT(); }
        CP_WAIT(1);
        __syncthreads();

        const uint32_t ksb = smb + (uint32_t)((KOFF(bi) + loffT) * 2);
        const uint32_t vsb = smb + (uint32_t)((VOFF(bi) + loffT) * 2);

        float sacc[8][4];
#pragma unroll
        for (int j = 0; j < 8; j++)
            sacc[j][0] = sacc[j][1] = sacc[j][2] = sacc[j][3] = 0.f;
#pragma unroll
        for (int j2 = 0; j2 < 4; j2++) {
#pragma unroll
            for (int kk = 0; kk < 4; kk++) {
                unsigned b0, b1, b2, b3;
                ldsm_x4(b0, b1, b2, b3,
                        ksb + (uint32_t)((j2 * 16 * TKSTR + kk * 16) * 2));
                mma_f16(sacc[2 * j2],     qf[kk], b0, b1);
                mma_f16(sacc[2 * j2 + 1], qf[kk], b2, b3);
            }
        }

        float mA = sacc[0][0], mB = sacc[0][2];
#pragma unroll
        for (int j = 0; j < 8; j++) {
            mA = fmaxf(mA, fmaxf(sacc[j][0], sacc[j][1]));
            mB = fmaxf(mB, fmaxf(sacc[j][2], sacc[j][3]));
        }
        mA = fmaxf(mA, __shfl_xor_sync(0xffffffffu, mA, 1));
        mA = fmaxf(mA, __shfl_xor_sync(0xffffffffu, mA, 2));
        mB = fmaxf(mB, __shfl_xor_sync(0xffffffffu, mB, 1));
        mB = fmaxf(mB, __shfl_xor_sync(0xffffffffu, mB, 2));
        const float mnA = fmaxf(mrow[0], mA);
        const float mnB = fmaxf(mrow[1], mB);
        const float alA = exp2f(mrow[0] - mnA);
        const float alB = exp2f(mrow[1] - mnB);
        mrow[0] = mnA; mrow[1] = mnB;

        unsigned pA[8], pB[8];
        float sumA = 0.f, sumB = 0.f;
#pragma unroll
        for (int j = 0; j < 8; j++) {
            pA[j] = ex2_h2(sacc[j][0] - mnA, sacc[j][1] - mnA);
            pB[j] = ex2_h2(sacc[j][2] - mnB, sacc[j][3] - mnB);
            float2 fa = u32_to_f2(pA[j]);
            float2 fb = u32_to_f2(pB[j]);
            sumA += fa.x + fa.y;
            sumB += fb.x + fb.y;
        }
        sumA += __shfl_xor_sync(0xffffffffu, sumA, 1);
        sumA += __shfl_xor_sync(0xffffffffu, sumA, 2);
        sumB += __shfl_xor_sync(0xffffffffu, sumB, 1);
        sumB += __shfl_xor_sync(0xffffffffu, sumB, 2);
        lrow[0] = lrow[0] * alA + sumA;
        lrow[1] = lrow[1] * alB + sumB;

#pragma unroll
        for (int j = 0; j < 8; j++) {
            oacc[j][0] *= alA; oacc[j][1] *= alA;
            oacc[j][2] *= alB; oacc[j][3] *= alB;
        }

#pragma unroll
        for (int d2 = 0; d2 < 4; d2++) {
#pragma unroll
            for (int kk = 0; kk < 4; kk++) {
                unsigned b0, b1, b2, b3;
                ldsm_x4(b0, b1, b2, b3,
                        vsb + (uint32_t)((d2 * 16 * TKSTR + kk * 16) * 2));
                const unsigned af[4] = { pA[2 * kk], pB[2 * kk],
                                         pA[2 * kk + 1], pB[2 * kk + 1] };
                mma_f16(oacc[2 * d2],     af, b0, b1);
                mma_f16(oacc[2 * d2 + 1], af, b2, b3);
            }
        }
        __syncthreads();
    }

    const float invA = 1.f / lrow[0];
    const float invB = 1.f / lrow[1];
    const size_t tr = (size_t)b * SEQ + q0 + warp * 16 + r4;
    __half* ob = g_atth + tr * D_MODEL + h * HD;
#pragma unroll
    for (int j = 0; j < 8; j++) {
        const int cc = j * 8 + 2 * c4;
        *(__half2*)&ob[cc] = __floats2half2_rn(oacc[j][0] * invA, oacc[j][1] * invA);
        *(__half2*)&ob[8 * D_MODEL + cc] =
            __floats2half2_rn(oacc[j][2] * invB, oacc[j][3] * invB);
    }
#undef ASTAGE
}

// ---------------------------------------------------------------------------
extern "C" void kernel_launch(void* const* d_in, const int* in_sizes, int n_in,
                              void* d_out, int out_size)
{
    const float* x    = (const float*)d_in[0];
    const float* Wqkv = (const float*)d_in[1];
    const float* bqkv = (const float*)d_in[2];
    const float* Wout = (const float*)d_in[3];
    const float* bout = (const float*)d_in[4];
    float* out = (float*)d_out;

    __half *xh, *wqkvh, *wouth, *atth;
    cudaGetSymbolAddress((void**)&xh, g_xh);
    cudaGetSymbolAddress((void**)&wqkvh, g_wqkvh);
    cudaGetSymbolAddress((void**)&wouth, g_wouth);
    cudaGetSymbolAddress((void**)&atth, g_atth);

    cudaFuncSetAttribute(gemm_h_kernel,
                         cudaFuncAttributeMaxDynamicSharedMemorySize, GEMM_SMEM_BYTES);
    cudaFuncSetAttribute(attn_h_kernel,
                         cudaFuncAttributeMaxDynamicSharedMemorySize, ATT_SMEM_BYTES);

    // 0) pre-passes: pure fp32 -> fp16 conversions (no transposes)
    cvt_h_kernel<<<1184, 256>>>((const float4*)x, (uint4*)xh,
                                NTOK * D_MODEL / 8);
    cvt_h_kernel<<<1184, 256>>>((const float4*)Wqkv, (uint4*)wqkvh,
                                D_MODEL * QKV_LD / 8);
    cvt_h_kernel<<<592, 256>>>((const float4*)Wout, (uint4*)wouth,
                               D_MODEL * D_MODEL / 8);

    // 1) qkv projection
    {
        dim3 grid(QKV_LD / 128, NTOK / 128);   // (24, 32)
        gemm_h_kernel<<<grid, 128, GEMM_SMEM_BYTES>>>(
            xh, wqkvh, bqkv, nullptr, NTOK, QKV_LD, D_MODEL, 1);
    }
    // 2) attention
    {
        dim3 grid(SEQ / 64, NHEAD, BATCH);     // (32, 16, 2)
        attn_h_kernel<<<grid, 128, ATT_SMEM_BYTES>>>();
    }
    // 3) output projection (fp32)
    {
        dim3 grid(D_MODEL / 128, NTOK / 128);  // (8, 32)
        gemm_h_kernel<<<grid, 128, GEMM_SMEM_BYTES>>>(
            atth, wouth, bout, out, NTOK, D_MODEL, D_MODEL, 0);
    }
}

// round 16
// speedup vs baseline: 1.1558x; 1.0114x over previous
#include <cuda_runtime.h>
#include <cuda_fp16.h>
#include <math.h>
#include <stdint.h>

// Problem constants
#define D_MODEL 1024
#define NHEAD   16
#define HD      64
#define SEQ     2048
#define BATCH   2
#define NTOK    (BATCH * SEQ)          // 4096
#define QKV_LD  (3 * D_MODEL)          // 3072

// Q pre-scale: 1/sqrt(64) * log2(e)  (softmax done base-2)
#define QSCALE 0.18033688011112042f

// HBM scratch (no cudaMalloc allowed)
__device__ __half g_xh[(size_t)NTOK * D_MODEL];
__device__ __half g_wqkvh[(size_t)D_MODEL * QKV_LD];      // Wqkv fp16 [K][N]
__device__ __half g_wouth[(size_t)D_MODEL * D_MODEL];     // Wout fp16 [K][N]
__device__ __half g_qkvh[(size_t)NTOK * QKV_LD];          // Q(scaled)/K/V fp16
__device__ __half g_atth[(size_t)NTOK * D_MODEL];

// ---------------------------------------------------------------------------
__device__ __forceinline__ uint32_t smem_u32(const void* p) {
    uint32_t a;
    asm("{ .reg .u64 t; cvta.to.shared.u64 t, %1; cvt.u32.u64 %0, t; }"
        : "=r"(a) : "l"(p));
    return a;
}
__device__ __forceinline__ unsigned h2_to_u32(__half2 h) {
    return *reinterpret_cast<unsigned*>(&h);
}
__device__ __forceinline__ float2 u32_to_f2(unsigned u) {
    __half2 h = *reinterpret_cast<__half2*>(&u);
    return __half22float2(h);
}
__device__ __forceinline__ void mma_f16(float c[4], const unsigned a[4],
                                        unsigned b0, unsigned b1) {
    asm volatile(
        "mma.sync.aligned.m16n8k16.row.col.f32.f16.f16.f32 "
        "{%0,%1,%2,%3}, {%4,%5,%6,%7}, {%8,%9}, {%0,%1,%2,%3};"
        : "+f"(c[0]), "+f"(c[1]), "+f"(c[2]), "+f"(c[3])
        : "r"(a[0]), "r"(a[1]), "r"(a[2]), "r"(a[3]), "r"(b0), "r"(b1));
}
__device__ __forceinline__ void ldsm_x4(unsigned& r0, unsigned& r1,
                                        unsigned& r2, unsigned& r3, uint32_t a) {
    asm volatile("ldmatrix.sync.aligned.m8n8.x4.shared.b16 {%0,%1,%2,%3}, [%4];"
                 : "=r"(r0), "=r"(r1), "=r"(r2), "=r"(r3) : "r"(a));
}
__device__ __forceinline__ void ldsm_x4_t(unsigned& r0, unsigned& r1,
                                          unsigned& r2, unsigned& r3, uint32_t a) {
    asm volatile("ldmatrix.sync.aligned.m8n8.x4.trans.shared.b16 {%0,%1,%2,%3}, [%4];"
                 : "=r"(r0), "=r"(r1), "=r"(r2), "=r"(r3) : "r"(a));
}
__device__ __forceinline__ unsigned ex2_h2(float lo, float hi) {
    unsigned r;
    asm("{\n\t.reg .b32 t;\n\tcvt.rn.f16x2.f32 t, %2, %1;\n\t"
        "ex2.approx.f16x2 %0, t;\n\t}"
        : "=r"(r) : "f"(lo), "f"(hi));
    return r;
}
#define CP16(dst, src) \
    asm volatile("cp.async.cg.shared.global [%0], [%1], 16;" \
                 :: "r"(dst), "l"(src) : "memory")
#define CP_COMMIT() asm volatile("cp.async.commit_group;" ::: "memory")
#define CP_WAIT(n)  asm volatile("cp.async.wait_group %0;" :: "n"(n) : "memory")

// ---------------------------------------------------------------------------
// Pre-pass: pure elementwise fp32 -> fp16
// ---------------------------------------------------------------------------
__global__ __launch_bounds__(256) void cvt_h_kernel(
    const float4* __restrict__ src, uint4* __restrict__ dst, int n8)
{
    for (int i = blockIdx.x * 256 + threadIdx.x; i < n8; i += gridDim.x * 256) {
        float4 a = src[2 * i], b = src[2 * i + 1];
        uint4 o;
        o.x = h2_to_u32(__floats2half2_rn(a.x, a.y));
        o.y = h2_to_u32(__floats2half2_rn(a.z, a.w));
        o.z = h2_to_u32(__floats2half2_rn(b.x, b.y));
        o.w = h2_to_u32(__floats2half2_rn(b.z, b.w));
        dst[i] = o;
    }
}

// ---------------------------------------------------------------------------
// FP16 mma GEMM: CTA 128x128, 4 warps of 64x64, cp.async 4-stage, K-chunk 32.
// As [m][k] stride 40; Bs [k][n] stride 136, B frags via ldmatrix.trans.
// mode 0: fp32 out.  mode 1: qkv (Q scaled by QSCALE; K and V plain fp16,
// all written coalesced to g_qkvh).
// ---------------------------------------------------------------------------
#define HSTR 40
#define BSTR 136
#define A_ST_H (128 * HSTR)              // 5120 half
#define B_ST_H (32 * BSTR)               // 4352 half
#define STG_H  (A_ST_H + B_ST_H)         // 9472 half per stage
#define GEMM_SMEM_BYTES (4 * STG_H * 2)  // 75776

__global__ __launch_bounds__(128, 2) void gemm_h_kernel(
    const __half* __restrict__ A, const __half* __restrict__ B,
    const float* __restrict__ bias, void* __restrict__ Cout,
    int M, int N, int K, int mode)
{
    extern __shared__ __half smh[];
    const uint32_t smb = smem_u32(smh);

    const int tid  = threadIdx.x;
    const int lane = tid & 31;
    const int warp = tid >> 5;
    const int r4 = lane >> 2;
    const int c4 = lane & 3;
    const int wrow = (warp >> 1) * 64;
    const int wcol = (warp & 1) * 64;
    const int row0 = blockIdx.y * 128;
    const int col0 = blockIdx.x * 128;

    const __half* Ablk = A + (size_t)row0 * K;
    const __half* Bblk = B + col0;

    const uint32_t loffA = (uint32_t)((lane & 15) * HSTR + (lane >> 4) * 8);
    const uint32_t loffB = (uint32_t)((lane & 15) * BSTR + (lane >> 4) * 8);

#define GSTAGE(c, st) do {                                                   \
        const __half* Ag = Ablk + (c) * 32;                                  \
        const __half* Bg = Bblk + (size_t)((c) * 32) * N;                    \
        _Pragma("unroll")                                                    \
        for (int i = 0; i < 4; i++) {                                        \
            const int id = tid + 128 * i;                                    \
            const int r = id >> 2, ch = id & 3;                              \
            CP16(smb + (uint32_t)(((st) * STG_H + r * HSTR + ch * 8) * 2),   \
                 Ag + (size_t)r * K + ch * 8);                               \
            const int rk = id >> 4, chb = id & 15;                           \
            CP16(smb + (uint32_t)(((st) * STG_H + A_ST_H + rk * BSTR + chb * 8) * 2), \
                 Bg + (size_t)rk * N + chb * 8);                             \
        }                                                                    \
        CP_COMMIT();                                                         \
    } while (0)

    float acc[4][8][4];
#pragma unroll
    for (int mf = 0; mf < 4; mf++)
#pragma unroll
        for (int nf = 0; nf < 8; nf++)
#pragma unroll
            for (int x = 0; x < 4; x++) acc[mf][nf][x] = 0.f;

    const int nchunk = K / 32;
    GSTAGE(0, 0);
    GSTAGE(1, 1);
    GSTAGE(2, 2);

    for (int c = 0; c < nchunk; c++) {
        CP_WAIT(2);
        __syncthreads();

        const uint32_t stA = smb + (uint32_t)(((c & 3) * STG_H) * 2);
        const uint32_t stB = stA + (uint32_t)(A_ST_H * 2);

#pragma unroll
        for (int ks = 0; ks < 2; ks++) {
            unsigned af[4][4];
            const uint32_t aB = stA + (uint32_t)((wrow * HSTR + ks * 16 + loffA) * 2);
#pragma unroll
            for (int mf = 0; mf < 4; mf++)
                ldsm_x4(af[mf][0], af[mf][1], af[mf][2], af[mf][3],
                        aB + (uint32_t)(mf * 16 * HSTR * 2));
            unsigned bf0[8], bf1[8];
            const uint32_t bB = stB + (uint32_t)((ks * 16 * BSTR + wcol + loffB) * 2);
#pragma unroll
            for (int np = 0; np < 4; np++) {
                unsigned r0, r1, r2, r3;
                ldsm_x4_t(r0, r1, r2, r3, bB + (uint32_t)(np * 16 * 2));
                bf0[2 * np] = r0; bf1[2 * np] = r1;
                bf0[2 * np + 1] = r2; bf1[2 * np + 1] = r3;
            }
#pragma unroll
            for (int nf = 0; nf < 8; nf++)
#pragma unroll
                for (int mf = 0; mf < 4; mf++)
                    mma_f16(acc[mf][nf], af[mf], bf0[nf], bf1[nf]);
        }

        if (c + 3 < nchunk) { GSTAGE(c + 3, (c + 3) & 3); }
        else { CP_COMMIT(); }
    }

    // ---- epilogue ----
    if (mode == 0) {
        float* C = (float*)Cout;
#pragma unroll
        for (int mf = 0; mf < 4; mf++) {
            const int r = row0 + wrow + mf * 16 + r4;
#pragma unroll
            for (int nf = 0; nf < 8; nf++) {
                const int cc = col0 + wcol + nf * 8 + 2 * c4;
                const float bx = bias[cc], by = bias[cc + 1];
                *(float2*)&C[(size_t)r * N + cc] =
                    make_float2(acc[mf][nf][0] + bx, acc[mf][nf][1] + by);
                *(float2*)&C[(size_t)(r + 8) * N + cc] =
                    make_float2(acc[mf][nf][2] + bx, acc[mf][nf][3] + by);
            }
        }
    } else {
        // qkv: Q section scaled; K and V plain. All coalesced half2 stores.
        const int cb  = col0 + wcol;
        const int sec = (cb % 192) / 64;    // 0=Q, 1=K, 2=V
        const float sc = (sec == 0) ? QSCALE : 1.0f;
#pragma unroll
        for (int mf = 0; mf < 4; mf++) {
            const int r = row0 + wrow + mf * 16 + r4;
#pragma unroll
            for (int nf = 0; nf < 8; nf++) {
                const int cc = cb + nf * 8 + 2 * c4;
                const float bx = bias[cc], by = bias[cc + 1];
                __half2 v0 = __floats2half2_rn((acc[mf][nf][0] + bx) * sc,
                                               (acc[mf][nf][1] + by) * sc);
                __half2 v1 = __floats2half2_rn((acc[mf][nf][2] + bx) * sc,
                                               (acc[mf][nf][3] + by) * sc);
                *(__half2*)&g_qkvh[(size_t)r * QKV_LD + cc] = v0;
                *(__half2*)&g_qkvh[(size_t)(r + 8) * QKV_LD + cc] = v1;
            }
        }
    }
#undef GSTAGE
}

// ---------------------------------------------------------------------------
// FlashAttention fp16 mma: P in registers, base-2 softmax via ex2.approx.f16x2,
// LDSM K frags; V consumed ROW-MAJOR [key][d] via ldmatrix.trans (no g_vt).
// 4 warps x 16 q = 64 q/CTA, 64-key tiles, cp.async double-buffered K & V.
// smem (half): K0 K1 V0 V1, each 64*72 = 4608 -> 18432 half = 36864 B.
// ---------------------------------------------------------------------------
#define TKSTR 72
#define KOFF(bi) ((bi) * 4608)
#define VOFF(bi) (9216 + (bi) * 4608)
#define ATT_SMEM_BYTES (18432 * 2)

__global__ __launch_bounds__(128, 3) void attn_h_kernel()
{
    extern __shared__ __half smh[];
    const uint32_t smb = smem_u32(smh);
    const int tid  = threadIdx.x;
    const int lane = tid & 31;
    const int warp = tid >> 5;
    const int b  = blockIdx.z;
    const int h  = blockIdx.y;
    const int q0 = blockIdx.x * 64;
    const int r4 = lane >> 2;
    const int c4 = lane & 3;

    // K (non-trans B frags): loffK as before
    const uint32_t loffK = (uint32_t)(((lane >> 4) * 8 + (lane & 7)) * TKSTR
                                      + ((lane >> 3) & 1) * 8);
    // V (trans B frags from [key][d]): GEMM-B style lane offset
    const uint32_t loffV = (uint32_t)((lane & 15) * TKSTR + (lane >> 4) * 8);

    unsigned qf[4][4];
    {
        const __half* qr  = g_qkvh + (size_t)(b * SEQ + q0 + warp * 16 + r4) * QKV_LD + h * 192;
        const __half* qr8 = qr + (size_t)8 * QKV_LD;
#pragma unroll
        for (int kk = 0; kk < 4; kk++) {
            const int k0 = kk * 16 + 2 * c4;
            qf[kk][0] = *(const unsigned*)(qr + k0);
            qf[kk][1] = *(const unsigned*)(qr8 + k0);
            qf[kk][2] = *(const unsigned*)(qr + k0 + 8);
            qf[kk][3] = *(const unsigned*)(qr8 + k0 + 8);
        }
    }

    const __half* Kg = g_qkvh + (size_t)b * SEQ * QKV_LD + h * 192 + 64;
    const __half* Vg = g_qkvh + (size_t)b * SEQ * QKV_LD + h * 192 + 128;

#define ASTAGE(t, bi) do {                                                   \
        const __half* Kt = Kg + (size_t)(t) * 64 * QKV_LD;                   \
        const __half* Vt = Vg + (size_t)(t) * 64 * QKV_LD;                   \
        _Pragma("unroll")                                                    \
        for (int i = 0; i < 4; i++) {                                        \
            const int id = tid + 128 * i;                                    \
            const int r = id >> 3, ch = id & 7;                              \
            CP16(smb + (uint32_t)((KOFF(bi) + r * TKSTR + ch * 8) * 2),      \
                 Kt + (size_t)r * QKV_LD + ch * 8);                          \
            CP16(smb + (uint32_t)((VOFF(bi) + r * TKSTR + ch * 8) * 2),      \
                 Vt + (size_t)r * QKV_LD + ch * 8);                          \
        }                                                                    \
        CP_COMMIT();                                                         \
    } while (0)

    float oacc[8][4];
#pragma unroll
    for (int j = 0; j < 8; j++)
#pragma unroll
        for (int x = 0; x < 4; x++) oacc[j][x] = 0.f;
    float mrow[2] = {-INFINITY, -INFINITY};
    float lrow[2] = {0.f, 0.f};

    const int ntile = SEQ / 64;   // 32
    ASTAGE(0, 0);

    for (int t = 0; t < ntile; t++) {
        const int bi = t & 1;
        if (t + 1 < ntile) { ASTAGE(t + 1, bi ^ 1); }
        else { CP_COMMIT(); }
        CP_WAIT(1);
        __syncthreads();

        const uint32_t ksb = smb + (uint32_t)((KOFF(bi) + loffK) * 2);
        const uint32_t vsb = smb + (uint32_t)((VOFF(bi) + loffV) * 2);

        // ---- S = Q @ K^T ----
        float sacc[8][4];
#pragma unroll
        for (int j = 0; j < 8; j++)
            sacc[j][0] = sacc[j][1] = sacc[j][2] = sacc[j][3] = 0.f;
#pragma unroll
        for (int j2 = 0; j2 < 4; j2++) {
#pragma unroll
            for (int kk = 0; kk < 4; kk++) {
                unsigned b0, b1, b2, b3;
                ldsm_x4(b0, b1, b2, b3,
                        ksb + (uint32_t)((j2 * 16 * TKSTR + kk * 16) * 2));
                mma_f16(sacc[2 * j2],     qf[kk], b0, b1);
                mma_f16(sacc[2 * j2 + 1], qf[kk], b2, b3);
            }
        }

        // ---- online softmax (base-2) ----
        float mA = sacc[0][0], mB = sacc[0][2];
#pragma unroll
        for (int j = 0; j < 8; j++) {
            mA = fmaxf(mA, fmaxf(sacc[j][0], sacc[j][1]));
            mB = fmaxf(mB, fmaxf(sacc[j][2], sacc[j][3]));
        }
        mA = fmaxf(mA, __shfl_xor_sync(0xffffffffu, mA, 1));
        mA = fmaxf(mA, __shfl_xor_sync(0xffffffffu, mA, 2));
        mB = fmaxf(mB, __shfl_xor_sync(0xffffffffu, mB, 1));
        mB = fmaxf(mB, __shfl_xor_sync(0xffffffffu, mB, 2));
        const float mnA = fmaxf(mrow[0], mA);
        const float mnB = fmaxf(mrow[1], mB);
        const float alA = exp2f(mrow[0] - mnA);
        const float alB = exp2f(mrow[1] - mnB);
        mrow[0] = mnA; mrow[1] = mnB;

        unsigned pA[8], pB[8];
        float sumA = 0.f, sumB = 0.f;
#pragma unroll
        for (int j = 0; j < 8; j++) {
            pA[j] = ex2_h2(sacc[j][0] - mnA, sacc[j][1] - mnA);
            pB[j] = ex2_h2(sacc[j][2] - mnB, sacc[j][3] - mnB);
            float2 fa = u32_to_f2(pA[j]);
            float2 fb = u32_to_f2(pB[j]);
            sumA += fa.x + fa.y;
            sumB += fb.x + fb.y;
        }
        sumA += __shfl_xor_sync(0xffffffffu, sumA, 1);
        sumA += __shfl_xor_sync(0xffffffffu, sumA, 2);
        sumB += __shfl_xor_sync(0xffffffffu, sumB, 1);
        sumB += __shfl_xor_sync(0xffffffffu, sumB, 2);
        lrow[0] = lrow[0] * alA + sumA;
        lrow[1] = lrow[1] * alB + sumB;

#pragma unroll
        for (int j = 0; j < 8; j++) {
            oacc[j][0] *= alA; oacc[j][1] *= alA;
            oacc[j][2] *= alB; oacc[j][3] *= alB;
        }

        // ---- O += P @ V  (V row-major [key][d], frags via ldmatrix.trans) ----
#pragma unroll
        for (int d2 = 0; d2 < 4; d2++) {
#pragma unroll
            for (int kk = 0; kk < 4; kk++) {
                unsigned b0, b1, b2, b3;
                ldsm_x4_t(b0, b1, b2, b3,
                          vsb + (uint32_t)((kk * 16 * TKSTR + d2 * 16) * 2));
                const unsigned af[4] = { pA[2 * kk], pB[2 * kk],
                                         pA[2 * kk + 1], pB[2 * kk + 1] };
                mma_f16(oacc[2 * d2],     af, b0, b1);
                mma_f16(oacc[2 * d2 + 1], af, b2, b3);
            }
        }
        __syncthreads();
    }

    const float invA = 1.f / lrow[0];
    const float invB = 1.f / lrow[1];
    const size_t tr = (size_t)b * SEQ + q0 + warp * 16 + r4;
    __half* ob = g_atth + tr * D_MODEL + h * HD;
#pragma unroll
    for (int j = 0; j < 8; j++) {
        const int cc = j * 8 + 2 * c4;
        *(__half2*)&ob[cc] = __floats2half2_rn(oacc[j][0] * invA, oacc[j][1] * invA);
        *(__half2*)&ob[8 * D_MODEL + cc] =
            __floats2half2_rn(oacc[j][2] * invB, oacc[j][3] * invB);
    }
#undef ASTAGE
}

// ---------------------------------------------------------------------------
extern "C" void kernel_launch(void* const* d_in, const int* in_sizes, int n_in,
                              void* d_out, int out_size)
{
    const float* x    = (const float*)d_in[0];
    const float* Wqkv = (const float*)d_in[1];
    const float* bqkv = (const float*)d_in[2];
    const float* Wout = (const float*)d_in[3];
    const float* bout = (const float*)d_in[4];
    float* out = (float*)d_out;

    __half *xh, *wqkvh, *wouth, *atth;
    cudaGetSymbolAddress((void**)&xh, g_xh);
    cudaGetSymbolAddress((void**)&wqkvh, g_wqkvh);
    cudaGetSymbolAddress((void**)&wouth, g_wouth);
    cudaGetSymbolAddress((void**)&atth, g_atth);

    cudaFuncSetAttribute(gemm_h_kernel,
                         cudaFuncAttributeMaxDynamicSharedMemorySize, GEMM_SMEM_BYTES);
    cudaFuncSetAttribute(attn_h_kernel,
                         cudaFuncAttributeMaxDynamicSharedMemorySize, ATT_SMEM_BYTES);

    // 0) pre-passes: pure fp32 -> fp16 conversions
    cvt_h_kernel<<<1184, 256>>>((const float4*)x, (uint4*)xh,
                                NTOK * D_MODEL / 8);
    cvt_h_kernel<<<1184, 256>>>((const float4*)Wqkv, (uint4*)wqkvh,
                                D_MODEL * QKV_LD / 8);
    cvt_h_kernel<<<592, 256>>>((const float4*)Wout, (uint4*)wouth,
                               D_MODEL * D_MODEL / 8);

    // 1) qkv projection (Q scaled; K, V plain; all coalesced)
    {
        dim3 grid(QKV_LD / 128, NTOK / 128);   // (24, 32)
        gemm_h_kernel<<<grid, 128, GEMM_SMEM_BYTES>>>(
            xh, wqkvh, bqkv, nullptr, NTOK, QKV_LD, D_MODEL, 1);
    }
    // 2) attention
    {
        dim3 grid(SEQ / 64, NHEAD, BATCH);     // (32, 16, 2)
        attn_h_kernel<<<grid, 128, ATT_SMEM_BYTES>>>();
    }
    // 3) output projection (fp32)
    {
        dim3 grid(D_MODEL / 128, NTOK / 128);  // (8, 32)
        gemm_h_kernel<<<grid, 128, GEMM_SMEM_BYTES>>>(
            atth, wouth, bout, out, NTOK, D_MODEL, D_MODEL, 0);
    }
}